// round 9
// baseline (speedup 1.0000x reference)
#include <cuda_runtime.h>
#include <cstdint>

// Problem constants
#define Bv    256
#define Mv    48
#define EPM   (Mv*(Mv-1))          // 2256 edges per molecule
#define Ev    (Bv*EPM)             // 577536 edges
#define Nv    (Bv*Mv)              // 12288 atoms
#define FEAT  57                    // 32 rbf + 25 sh
#define HSv   128

#define EBLK  64                    // threads per edge block (1 edge/thread)
#define EMB_BLOCKS  192             // scheduled FIRST (wave 1)
#define ROWS_PER_EMB_BLOCK (Nv / EMB_BLOCKS)   // 64 rows/block, 2 warps -> 32/warp
#define EDGE_BLOCKS (Ev / EBLK)     // 9024

#define TILE_BYTES (EBLK * FEAT * 4) // 14592, multiple of 16

// Output layout (flattened reference tuple, float32):
//   feat [E,57] | node_emb [N,128] | edge_index [2,E] | transpose_index [E]
#define OFF_EMB  ((size_t)Ev*FEAT)               // 32919552
#define OFF_EI   (OFF_EMB + (size_t)Nv*HSv)      // 34492416
#define OFF_TR   (OFF_EI + 2*(size_t)Ev)         // 35647488

__constant__ float SH_COEF[25] = {
    1.0f,
    1.7320508f, 1.7320508f, 1.7320508f,
    0.64549722f, 1.2909944f, 2.2360680f, 1.2909944f, 0.64549722f,
    0.13944334f, 0.34156503f, 1.0801234f, 2.6457513f, 1.0801234f, 0.34156503f, 0.13944334f,
    0.021128856f, 0.059761430f, 0.22360680f, 0.94868330f, 3.0f,
    0.94868330f, 0.22360680f, 0.059761430f, 0.021128856f
};

__constant__ float BINOM31[32] = {
    1.f, 31.f, 465.f, 4495.f, 31465.f, 169911.f, 736281.f, 2629575.f,
    7888725.f, 20160075.f, 44352165.f, 84672315.f, 141120525.f, 206253075.f,
    265182525.f, 300540195.f, 300540195.f, 265182525.f, 206253075.f, 141120525.f,
    84672315.f, 44352165.f, 20160075.f, 7888725.f, 2629575.f, 736281.f,
    169911.f, 31465.f, 4495.f, 465.f, 31.f, 1.f
};

__device__ __forceinline__ uint32_t smem_u32(const void* p) {
    uint32_t a;
    asm("{ .reg .u64 t; cvta.to.shared.u64 t, %1; cvt.u32.u64 %0, t; }"
        : "=r"(a) : "l"(p));
    return a;
}

__global__ __launch_bounds__(EBLK)
void fused_kernel(const float* __restrict__ pos,
                  const int*   __restrict__ an,
                  const float* __restrict__ table,
                  const float* __restrict__ alphap,
                  float* __restrict__ out)
{
    __shared__ __align__(16) float stage[EBLK * FEAT];   // 14592 B

    const int tid = threadIdx.x;

    if (blockIdx.x < EMB_BLOCKS) {
        // ---------- Embedding path: first-wave blocks, batched gathers (MLP=4) ----
        const int lane = tid & 31;
        const int wrp  = tid >> 5;                          // 0..1
        const int base = blockIdx.x * ROWS_PER_EMB_BLOCK + wrp * 32;
        #pragma unroll
        for (int i = 0; i < 32; i += 4) {
            int   t[4];
            float4 v[4];
            #pragma unroll
            for (int j = 0; j < 4; j++) t[j] = __ldg(an + base + i + j);
            #pragma unroll
            for (int j = 0; j < 4; j++)
                v[j] = ((const float4*)(table + (size_t)t[j] * HSv))[lane];
            #pragma unroll
            for (int j = 0; j < 4; j++)
                ((float4*)(out + OFF_EMB + (size_t)(base + i + j) * HSv))[lane] = v[j];
        }
        return;
    }

    // ---------- Edge path ----------
    const int eb = blockIdx.x - EMB_BLOCKS;
    const int e  = eb * EBLK + tid;

    // Decompose edge id -> (molecule b, src-local s, k), dst-local d
    const int b   = e / EPM;
    const int rem = e - b * EPM;
    const int s   = rem / (Mv - 1);
    const int k   = rem - s * (Mv - 1);
    const int d   = k + (k >= s);
    const int src = b * Mv + s;
    const int dst = b * Mv + d;

    const float ex = __ldg(pos + 3*dst + 0) - __ldg(pos + 3*src + 0);
    const float ey = __ldg(pos + 3*dst + 1) - __ldg(pos + 3*src + 1);
    const float ez = __ldg(pos + 3*dst + 2) - __ldg(pos + 3*src + 2);

    const float r2 = ex*ex + ey*ey + ez*ez;
    float r = sqrtf(r2);
    r = fmaxf(r, 1e-6f);
    const float inv = 1.0f / r;
    const float ux = ex * inv, uy = ey * inv, uz = ez * inv;

    float* row = &stage[tid * FEAT];

    // ---- RBF: exponential Bernstein + bump cutoff ----
    // arg_k = (31-k)*xx + k*logem = 31*xx + k*dd, dd = logem - xx, monotone in k.
    // Run a multiplicative chain from the MAX end with ratio = exp(-|dd|) <= 1:
    // no overflow, underflow only where the reference's exp() also underflows.
    {
        const float aeff  = 0.5f * __ldg(alphap);
        const float xx    = -aeff * r;
        const float em    = -expm1f(xx);          // in (0,1)
        const float logem = __logf(em);
        const float dd    = logem - xx;

        const float rc = r * (1.0f / 15.0f);
        float fcut = 0.0f;
        if (rc < 1.0f) {
            const float den = fmaxf((1.0f - rc) * (1.0f + rc), 1e-9f);
            fcut = __expf(-rc * rc / den);
        }

        const float ratio = __expf(-fabsf(dd));
        if (dd >= 0.0f) {
            // max at k=31, run downward
            float t = fcut * __expf(31.0f * logem);
            #pragma unroll
            for (int kk = 31; kk >= 0; kk--) {
                row[kk] = BINOM31[kk] * t;
                t *= ratio;
            }
        } else {
            // max at k=0, run upward
            float t = fcut * __expf(31.0f * xx);
            #pragma unroll
            for (int kk = 0; kk < 32; kk++) {
                row[kk] = BINOM31[kk] * t;
                t *= ratio;
            }
        }
    }

    // ---- Real spherical harmonics up to l=4 (component norm) ----
    {
        float Cc[5], Ss[5];
        Cc[0] = 1.0f; Ss[0] = 0.0f;
        #pragma unroll
        for (int m = 1; m < 5; m++) {
            Cc[m] = Cc[m-1]*ux - Ss[m-1]*uy;
            Ss[m] = Ss[m-1]*ux + Cc[m-1]*uy;
        }

        float Q[5][5];
        Q[0][0] = 1.0f;
        #pragma unroll
        for (int m = 0; m < 5; m++) {
            if (m > 0) Q[m][m] = Q[m-1][m-1] * (float)(2*m - 1);   // (2m-1)!!
            if (m < 4) Q[m+1][m] = (float)(2*m + 1) * uz * Q[m][m];
            #pragma unroll
            for (int l = m + 2; l < 5; l++)
                Q[l][m] = ((float)(2*l - 1) * uz * Q[l-1][m]
                           - (float)(l - 1 + m) * Q[l-2][m]) * (1.0f / (float)(l - m));
        }

        int idx = 0;
        #pragma unroll
        for (int l = 0; l < 5; l++) {
            #pragma unroll
            for (int m = -l; m <= l; m++) {
                const int am = (m < 0) ? -m : m;
                const float ang = (m < 0) ? Ss[am] : Cc[am];
                row[32 + idx] = SH_COEF[idx] * Q[l][am] * ang;
                idx++;
            }
        }
    }

    // ---- Index outputs (coalesced STG) ----
    out[OFF_EI + e]      = (float)dst;
    out[OFF_EI + Ev + e] = (float)src;
    const int tr = b * EPM + d * (Mv - 1) + s - (d < s);
    out[OFF_TR + e] = (float)tr;

    __syncthreads();

    // ---- TMA 1-D bulk store: smem tile -> gmem (no LSU traffic) ----
    if (tid == 0) {
        asm volatile("fence.proxy.async.shared::cta;" ::: "memory");
        const uint32_t src_s = smem_u32(stage);
        void* dstg = (void*)(out + (size_t)eb * (EBLK * FEAT));
        asm volatile(
            "cp.async.bulk.global.shared::cta.bulk_group [%0], [%1], %2;"
            :: "l"(dstg), "r"(src_s), "n"(TILE_BYTES) : "memory");
        asm volatile("cp.async.bulk.commit_group;" ::: "memory");
        asm volatile("cp.async.bulk.wait_group 0;" ::: "memory");
    }
}

extern "C" void kernel_launch(void* const* d_in, const int* in_sizes, int n_in,
                              void* d_out, int out_size)
{
    const float* pos    = (const float*)d_in[0];
    const int*   an     = (const int*)d_in[1];
    const float* table  = (const float*)d_in[2];
    const float* alphap = (const float*)d_in[3];
    float* out = (float*)d_out;

    // Maximize shared-memory carveout so 14.6KB blocks co-reside ~15x.
    static bool attr_done = false;
    if (!attr_done) {
        cudaFuncSetAttribute(fused_kernel,
                             cudaFuncAttributePreferredSharedMemoryCarveout, 100);
        attr_done = true;
    }

    fused_kernel<<<EMB_BLOCKS + EDGE_BLOCKS, EBLK>>>(pos, an, table, alphap, out);
}